// round 14
// baseline (speedup 1.0000x reference)
#include <cuda_runtime.h>
#include <cuda_bf16.h>
#include <cstdint>

#define W 256
#define BH 64
#define NBLOCKS 512           // 128 images * 4 bands
#define MAGF 516              // floats per mag slot (258 float2)

__device__ float g_partials[NBLOCKS];
__device__ unsigned int g_ticket;   // zero-init; atomicInc wraps after NBLOCKS -> graph-replay safe

// Gaussian taps as numpy computes them (f64 exp, f64 normalize)
constexpr double E2d  = 0.1353352832366127;   // exp(-2)
constexpr double E05d = 0.6065306597126334;   // exp(-0.5)
constexpr double GSUM = 1.0 + 2.0 * (E2d + E05d);
constexpr float  G0f = (float)(E2d / GSUM);
constexpr float  G1f = (float)(E05d / GSUM);
constexpr float  G2f = (float)(1.0 / GSUM);

// Fused vertical taps (Gv conv Sobel-vertical), applied to A/B row rings:
// sym (for gx over B): C0..C3 ; antisym (for gy over A): D1..D3
constexpr float C0 = (float)(2.0 * (E05d + 1.0) / GSUM);
constexpr float C1 = (float)((E2d + 2.0 * E05d + 1.0) / GSUM);
constexpr float C2 = (float)((2.0 * E2d + E05d) / GSUM);
constexpr float C3 = (float)(E2d / GSUM);
constexpr float D1 = (float)((1.0 - E2d) / GSUM);    // G2 - G0
constexpr float D2 = (float)(E05d / GSUM);           // G1
constexpr float D3 = (float)(E2d / GSUM);            // G0

// Quadrant-exact tangent thresholds for k = 4 + round(atan2(gy,gx)*4/3.14159)
#define TLO_POS 0.414213174f
#define THI_POS 2.414206767f
#define TLO_NEG 0.414216283f
#define THI_NEG 2.414224887f

__device__ __forceinline__ int dir_idx(float gx, float gy) {
    float ax = fabsf(gx), ay = fabsf(gy);
    bool xn = gx < 0.0f;
    float tlo = xn ? TLO_NEG : TLO_POS;
    float thi = xn ? THI_NEG : THI_POS;
    int s = (ay >= ax * tlo) ? ((ay > ax * thi) ? 2 : 1) : 0;
    int kp = xn ? (4 - s) : s;
    int k = (gy < 0.0f) ? (4 - kp) : (4 + kp);
    return k & 7;
}

// NMS neighbor offsets packed in nibbles: (dr+1),(dc+1) per idx (validated rel_err=0)
#define DRP 0x00012221u
#define DCP 0x21000122u

// Squared magnitudes; em4 = er&3 (compile-time). sqrtf only on pass (rare).
__device__ __forceinline__ float nms_one(float msq, int idx, const float* base, int em4) {
    int dr = (int)((DRP >> (idx * 4)) & 3u) - 1;
    int dc = (int)((DCP >> (idx * 4)) & 3u) - 1;
    float np = base[((em4 + dr) & 3) * MAGF + 2 * dc];
    float nn = base[((em4 - dr) & 3) * MAGF - 2 * dc];
    bool pass = (fminf(msq - np, msq - nn) > 0.0f) && (msq >= 4.0f);
    return pass ? sqrtf(msq) : 0.0f;
}

// float2 layout everywhere: .x = image0, .y = image1
__global__ __launch_bounds__(256, 4) void canny_fused(const float* __restrict__ in0,
                                                      const float* __restrict__ in1,
                                                      float* __restrict__ out) {
    const int t   = threadIdx.x;            // column
    const int blk = blockIdx.x;
    const int n   = blk >> 2;               // image
    const int r0  = (blk & 3) * BH;         // band start row (multiple of 64)
    const float* b0 = in0 + n * (W * W) + t;
    const float* b1 = in1 + n * (W * W) + t;

    __shared__ __align__(8) float2 sh_prep[4][W + 4];   // col c -> idx c+2; guards 0,1,W+2,W+3
    __shared__ __align__(8) float2 sh_h[2][W + 2];      // hblur rows; col c -> idx c+1
    __shared__ __align__(8) float2 sh_mag[4][W + 2];    // SQUARED mags; col c -> idx c+1
    __shared__ float  red[256];
    __shared__ double sdd[256];
    __shared__ unsigned s_last;

    // zero everything once (guards stay zero; data cells get overwritten)
    {
        float2 z = make_float2(0.f, 0.f);
        float2* zp = (float2*)sh_prep;
        for (int i = t; i < 4 * (W + 4); i += 256) zp[i] = z;
        float2* zh = (float2*)sh_h;
        for (int i = t; i < 2 * (W + 2); i += 256) zh[i] = z;
        float2* zm = (float2*)sh_mag;
        for (int i = t; i < 4 * (W + 2); i += 256) zm[i] = z;
    }

    // 8-deep register rings of Sobel row aggregates (slot = row & 7)
    float2 Ar[8], Br[8];
    #pragma unroll
    for (int i = 0; i < 8; i++) { Ar[i] = make_float2(0.f, 0.f); Br[i] = make_float2(0.f, 0.f); }

    float2 h_d1 = make_float2(0.f, 0.f);    // own hblur value of row ir-3 (A/B center tap)
    int d1i = 0, d2i = 0;                   // dirs (bits 0-7) + pass flag (bit 16)
    float acc = 0.f;

    const float* mbase0 = &sh_mag[0][t + 1].x;
    const float* mbase1 = &sh_mag[0][t + 1].y;

    // software prefetch of the current row, one iteration ahead
    float qa0 = 0.f, qa1 = 0.f;
    {
        const int irf = r0 - 8;
        if ((unsigned)irf < (unsigned)W) { qa0 = b0[irf * W]; qa1 = b1[irf * W]; }
    }

    __syncthreads();

    // 80 iterations: ir = r0-8 .. r0+BH+7.  r0 % 8 == 0 -> ir ≡ j (mod 8).
    // PRE : prefetch ir+1 | hblur ir-2 (prep slot (j+2)&3, written 2 iters ago) |
    //       STS h ir-2 (slot j&1) | A/B ir-3 (h slot (j+1)&1, written last iter;
    //       center h_d1) -> ring slot (j+5)&7 | fused-vertical gx/gy/msq row ir-6
    //       (ring slots (j+7),j..(j+5) &7) + border corrections | dir pack
    // POST: STS prep ir (slot j&3) | STS mag ir-6 (slot (j+2)&3) |
    //       NMS er = ir-8 (center slot j&3; neighbors (j+1)&3,(j+3)&3 — disjoint
    //       from this-iter mag write slot (j+2)&3)
    #pragma unroll 1
    for (int ir0 = r0 - 8; ir0 < r0 + BH + 8; ir0 += 8) {
        #pragma unroll
        for (int j = 0; j < 8; ++j) {
            const int ir = ir0 + j;

            // ---- prefetch row ir+1 (consumed next iteration) ----
            float qb0 = 0.f, qb1 = 0.f;
            {
                const int irn = ir + 1;
                if ((unsigned)irn < (unsigned)W) { qb0 = b0[irn * W]; qb1 = b1[irn * W]; }
            }

            // ---- hblur row ir-2 (prep slot written 2 iters ago; barrier between) ----
            float2 h;
            {
                const float2* pr = sh_prep[(j + 2) & 3];
                float2 a0 = pr[t], a1 = pr[t + 1], a2 = pr[t + 2], a3 = pr[t + 3], a4 = pr[t + 4];
                h.x = G0f * (a0.x + a4.x) + G1f * (a1.x + a3.x) + G2f * a2.x;
                h.y = G0f * (a0.y + a4.y) + G1f * (a1.y + a3.y) + G2f * a2.y;
            }
            sh_h[j & 1][t + 1] = h;   // (ir-2)&1 == j&1

            // ---- A/B aggregates row ir-3 (h slot written last iter; col clamp via guards) ----
            {
                const float2* hh = sh_h[(j + 1) & 1];
                float2 l = hh[t], r = hh[t + 2];
                float2 c = h_d1;
                float2 A, Bv;
                A.x  = l.x + 2.0f * c.x + r.x;   Bv.x = l.x - r.x;
                A.y  = l.y + 2.0f * c.y + r.y;   Bv.y = l.y - r.y;
                Ar[(j + 5) & 7] = A;             // (ir-3)&7 == (j+5)&7
                Br[(j + 5) & 7] = Bv;
            }
            h_d1 = h;

            // ---- fused vertical Sobel row mr = ir-6 (ring rows mr-3..mr+3) ----
            float2 nm = make_float2(0.f, 0.f);
            int ni = 0;
            {
                const int mr = ir - 6;
                if ((unsigned)mr < (unsigned)W) {
                    float gy0 = D3 * (Ar[(j + 7) & 7].x - Ar[(j + 5) & 7].x)
                              + D2 * (Ar[j & 7].x       - Ar[(j + 4) & 7].x)
                              + D1 * (Ar[(j + 1) & 7].x - Ar[(j + 3) & 7].x);
                    float gy1 = D3 * (Ar[(j + 7) & 7].y - Ar[(j + 5) & 7].y)
                              + D2 * (Ar[j & 7].y       - Ar[(j + 4) & 7].y)
                              + D1 * (Ar[(j + 1) & 7].y - Ar[(j + 3) & 7].y);
                    float gx0 = C3 * (Br[(j + 7) & 7].x + Br[(j + 5) & 7].x)
                              + C2 * (Br[j & 7].x       + Br[(j + 4) & 7].x)
                              + C1 * (Br[(j + 1) & 7].x + Br[(j + 3) & 7].x)
                              + C0 *  Br[(j + 2) & 7].x;
                    float gx1 = C3 * (Br[(j + 7) & 7].y + Br[(j + 5) & 7].y)
                              + C2 * (Br[j & 7].y       + Br[(j + 4) & 7].y)
                              + C1 * (Br[(j + 1) & 7].y + Br[(j + 3) & 7].y)
                              + C0 *  Br[(j + 2) & 7].y;
                    // exact border corrections: reference zero-clamps blurred(-1)/blurred(W)
                    if (mr == 0) {        // remove virtual blurred(-1) = G1*X(0)+G0*X(1)
                        gx0 -= G1f * Br[(j + 2) & 7].x + G0f * Br[(j + 3) & 7].x;
                        gx1 -= G1f * Br[(j + 2) & 7].y + G0f * Br[(j + 3) & 7].y;
                        gy0 -= G1f * Ar[(j + 2) & 7].x + G0f * Ar[(j + 3) & 7].x;
                        gy1 -= G1f * Ar[(j + 2) & 7].y + G0f * Ar[(j + 3) & 7].y;
                    }
                    if (mr == W - 1) {    // remove virtual blurred(W) = G1*X(W-1)+G0*X(W-2)
                        gx0 -= G1f * Br[(j + 2) & 7].x + G0f * Br[(j + 1) & 7].x;
                        gx1 -= G1f * Br[(j + 2) & 7].y + G0f * Br[(j + 1) & 7].y;
                        gy0 += G1f * Ar[(j + 2) & 7].x + G0f * Ar[(j + 1) & 7].x;
                        gy1 += G1f * Ar[(j + 2) & 7].y + G0f * Ar[(j + 1) & 7].y;
                    }
                    nm.x = gx0 * gx0 + gy0 * gy0;
                    nm.y = gx1 * gx1 + gy1 * gy1;
                    if (__any_sync(0xffffffffu, fmaxf(nm.x, nm.y) >= 4.0f))
                        ni = dir_idx(gx0, gy0) | (dir_idx(gx1, gy1) << 4) | 0x10000;
                }
            }

            __syncthreads();   // single barrier; post-barrier work is tiny

            // ---- STS prep row ir (transform inside guard: OOB rows store exact 0) ----
            {
                float2 p = make_float2(0.f, 0.f);
                if ((unsigned)ir < (unsigned)W)
                    p = make_float2((qa0 + 1.0f) * 0.5f, (qa1 + 1.0f) * 0.5f);
                sh_prep[j & 3][t + 2] = p;
            }

            // ---- STS mag row ir-6 (slot (j+2)&3) ----
            sh_mag[(j + 2) & 3][t + 1] = nm;

            // ---- NMS row er = ir-8 (center slot j&3); flag warp-uniform ----
            {
                const int er = ir - 8;
                if ((unsigned)(er - r0) < (unsigned)BH && (d2i & 0x10000)) {
                    float2 cm = sh_mag[j & 3][t + 1];   // own center mag^2
                    float e0 = nms_one(cm.x, d2i & 7,        mbase0, j & 3);
                    float e1 = nms_one(cm.y, (d2i >> 4) & 7, mbase1, j & 3);
                    acc += fabsf(e0 - e1);
                }
            }

            d2i = d1i; d1i = ni;
            qa0 = qb0; qa1 = qb1;
        }
    }

    // deterministic block reduction
    red[t] = acc;
    __syncthreads();
    #pragma unroll
    for (int off = 128; off > 0; off >>= 1) {
        if (t < off) red[t] += red[t + off];
        __syncthreads();
    }

    if (t == 0) {
        g_partials[blk] = red[0];
        __threadfence();
        unsigned old = atomicInc(&g_ticket, NBLOCKS - 1);   // wraps to 0 -> replay-safe
        s_last = (old == NBLOCKS - 1) ? 1u : 0u;
    }
    __syncthreads();

    // last block deterministically reduces all partials (double precision)
    if (s_last) {
        double s = 0.0;
        for (int i = t; i < NBLOCKS; i += 256) s += (double)__ldcg(&g_partials[i]);
        sdd[t] = s;
        __syncthreads();
        #pragma unroll
        for (int off = 128; off > 0; off >>= 1) {
            if (t < off) sdd[t] += sdd[t + off];
            __syncthreads();
        }
        if (t == 0) out[0] = (float)(sdd[0] / 8388608.0);
    }
}

extern "C" void kernel_launch(void* const* d_in, const int* in_sizes, int n_in,
                              void* d_out, int out_size) {
    const float* gt = (const float*)d_in[0];   // data_input
    const float* pr = (const float*)d_in[1];   // model_output
    canny_fused<<<NBLOCKS, 256>>>(gt, pr, (float*)d_out);
}

// round 15
// speedup vs baseline: 1.0622x; 1.0622x over previous
#include <cuda_runtime.h>
#include <cuda_bf16.h>
#include <cstdint>

#define W 256
#define BH 64
#define NBLOCKS 512           // 128 images * 4 bands
#define MAGF 516              // floats per mag slot (258 float2)

__device__ float g_partials[NBLOCKS];
__device__ unsigned int g_ticket;   // zero-init; atomicInc wraps after NBLOCKS -> graph-replay safe

// Gaussian taps as numpy computes them (f64 exp, f64 normalize)
constexpr double E2d  = 0.1353352832366127;   // exp(-2)
constexpr double E05d = 0.6065306597126334;   // exp(-0.5)
constexpr double GSUM = 1.0 + 2.0 * (E2d + E05d);
constexpr float  G0 = (float)(E2d / GSUM);
constexpr float  G1 = (float)(E05d / GSUM);
constexpr float  G2 = (float)(1.0 / GSUM);

// Quadrant-exact tangent thresholds for k = 4 + round(atan2(gy,gx)*4/3.14159)
#define TLO_POS 0.414213174f
#define THI_POS 2.414206767f
#define TLO_NEG 0.414216283f
#define THI_NEG 2.414224887f

__device__ __forceinline__ int dir_idx(float gx, float gy) {
    float ax = fabsf(gx), ay = fabsf(gy);
    bool xn = gx < 0.0f;
    float tlo = xn ? TLO_NEG : TLO_POS;
    float thi = xn ? THI_NEG : THI_POS;
    int s = (ay >= ax * tlo) ? ((ay > ax * thi) ? 2 : 1) : 0;
    int kp = xn ? (4 - s) : s;
    int k = (gy < 0.0f) ? (4 - kp) : (4 + kp);
    return k & 7;
}

// NMS neighbor offsets packed in nibbles: (dr+1),(dc+1) per idx (validated rel_err=0)
#define DRP 0x00012221u
#define DCP 0x21000122u

// Squared magnitudes; em4 = er&3 (compile-time). sqrtf only on pass (rare).
__device__ __forceinline__ float nms_one(float msq, int idx, const float* base, int em4) {
    int dr = (int)((DRP >> (idx * 4)) & 3u) - 1;
    int dc = (int)((DCP >> (idx * 4)) & 3u) - 1;
    float np = base[((em4 + dr) & 3) * MAGF + 2 * dc];
    float nn = base[((em4 - dr) & 3) * MAGF - 2 * dc];
    bool pass = (fminf(msq - np, msq - nn) > 0.0f) && (msq >= 4.0f);
    return pass ? sqrtf(msq) : 0.0f;
}

// float2 layout everywhere: .x = image0, .y = image1
__global__ __launch_bounds__(256, 4) void canny_fused(const float* __restrict__ in0,
                                                      const float* __restrict__ in1,
                                                      float* __restrict__ out) {
    const int t   = threadIdx.x;            // column
    const int blk = blockIdx.x;
    const int n   = blk >> 2;               // image
    const int r0  = (blk & 3) * BH;         // band start row (multiple of 64)
    const float* b0 = in0 + n * (W * W) + t;
    const float* b1 = in1 + n * (W * W) + t;

    __shared__ __align__(8) float2 sh_prep[4][W + 4];   // 4-slot ring; col c -> idx c+2
    __shared__ __align__(8) float2 sh_bl[4][W + 2];     // 4-slot ring; col c -> idx c+1
    __shared__ __align__(8) float2 sh_mag[4][W + 2];    // SQUARED mags; col c -> idx c+1
    __shared__ float  red[256];
    __shared__ double sdd[256];
    __shared__ unsigned s_last;

    // zero everything once (guards stay zero; data cells get overwritten)
    {
        float2 z = make_float2(0.f, 0.f);
        float2* zp = (float2*)sh_prep;
        for (int i = t; i < 4 * (W + 4); i += 256) zp[i] = z;
        float2* zb = (float2*)sh_bl;
        for (int i = t; i < 4 * (W + 2); i += 256) zb[i] = z;
        float2* zm = (float2*)sh_mag;
        for (int i = t; i < 4 * (W + 2); i += 256) zm[i] = z;
    }

    // register rings
    float2 hb0, hb1, hb2, hb3, hb4;                  // hblur rows ir-6..ir-2 (post-push)
    hb0 = hb1 = hb2 = hb3 = hb4 = make_float2(0.f, 0.f);
    // named A/B slots, indexed by (row & 3) at compile time (no ring shifts)
    float2 Ar0, Ar1, Ar2, Ar3, Br0, Br1, Br2, Br3;
    Ar0 = Ar1 = Ar2 = Ar3 = Br0 = Br1 = Br2 = Br3 = make_float2(0.f, 0.f);
    float2 v_d1 = make_float2(0.f, 0.f);             // vblur rows ir-5, ir-6 (delay line)
    float2 v_d2 = make_float2(0.f, 0.f);
    int d1i = 0, d2i = 0;                            // dirs (bits 0-7) + pass flag (bit 16)
    float acc = 0.f;

    const float* mbase0 = &sh_mag[0][t + 1].x;
    const float* mbase1 = &sh_mag[0][t + 1].y;

    // software prefetch of the current row, one iteration ahead
    float qa0 = 0.f, qa1 = 0.f;
    {
        const int irf = r0 - 6;
        if ((unsigned)irf < (unsigned)W) { qa0 = b0[irf * W]; qa1 = b1[irf * W]; }
    }

    __syncthreads();

    // 80 iterations: ir = r0-6 .. r0+BH+9.  r0 % 4 == 0  ->  ir ≡ (j+2) (mod 4).
    // PRE : prefetch ir+1 | hblur ir-2 (prep slot j&3, written 2 iters ago — one
    //       barrier between write@ir-2-post and read@ir-pre) | vblur ir-4 (regs) |
    //       A/B ir-6 (bl slot j&3, written 2 iters ago; center v_d2) -> named slot j&3 |
    //       magsq ir-7 (named slots (j+2),(j+3),j — rows ir-8..ir-6) | dir pack
    // POST: STS prep ir (slot (j+2)&3; rewritten @ir+4, read @ir+2 — separated) |
    //       STS bl ir-4 (slot (j+2)&3) | STS mag ir-7 (slot (j+3)&3) |
    //       NMS er = ir-9 (center slot (j+1)&3; reads slots {j,j+1,j+2}&3, all written
    //       in iters ir-3..ir-1, barrier-separated; disjoint from write slot (j+3)&3)
    #pragma unroll 1
    for (int ir0 = r0 - 6; ir0 < r0 + BH + 10; ir0 += 4) {
        #pragma unroll
        for (int j = 0; j < 4; ++j) {
            const int ir = ir0 + j;

            // ---- prefetch row ir+1 (consumed next iteration) ----
            float qb0 = 0.f, qb1 = 0.f;
            {
                const int irn = ir + 1;
                if ((unsigned)irn < (unsigned)W) { qb0 = b0[irn * W]; qb1 = b1[irn * W]; }
            }

            // ---- hblur row ir-2 (prep slot (ir-2)&3 = j&3, written 2 iters ago) ----
            float2 h;
            {
                const float2* pr = sh_prep[j & 3];
                float2 a0 = pr[t], a1 = pr[t + 1], a2 = pr[t + 2], a3 = pr[t + 3], a4 = pr[t + 4];
                h.x = G0 * (a0.x + a4.x) + G1 * (a1.x + a3.x) + G2 * a2.x;
                h.y = G0 * (a0.y + a4.y) + G1 * (a1.y + a3.y) + G2 * a2.y;
            }
            hb0 = hb1; hb1 = hb2; hb2 = hb3; hb3 = hb4; hb4 = h;
            // hb ring now holds rows ir-6..ir-2

            // ---- vblur row ir-4 (pure registers) ----
            float2 v = make_float2(0.f, 0.f);
            {
                const int br = ir - 4;
                if ((unsigned)br < (unsigned)W) {
                    v.x = G0 * (hb0.x + hb4.x) + G1 * (hb1.x + hb3.x) + G2 * hb2.x;
                    v.y = G0 * (hb0.y + hb4.y) + G1 * (hb1.y + hb3.y) + G2 * hb2.y;
                }
            }

            // ---- A/B aggregates row ir-6 (bl slot (ir-6)&3 = j&3, written 2 iters ago;
            //      center = own vblur from 2 iters ago) -> named slot (ir-6)&3 = j&3 ----
            {
                const float2* bl = sh_bl[j & 3];
                float2 l = bl[t], r = bl[t + 2];
                float2 c = v_d2;
                float2& Aw = (j & 3) == 0 ? Ar0 : (j & 3) == 1 ? Ar1
                           : (j & 3) == 2 ? Ar2 : Ar3;
                float2& Bw = (j & 3) == 0 ? Br0 : (j & 3) == 1 ? Br1
                           : (j & 3) == 2 ? Br2 : Br3;
                Aw.x = l.x + 2.0f * c.x + r.x;   Bw.x = l.x - r.x;
                Aw.y = l.y + 2.0f * c.y + r.y;   Bw.y = l.y - r.y;
            }
            v_d2 = v_d1;  v_d1 = v;

            // ---- Sobel + SQUARED magnitude row mr = ir-7 (rows ir-8..ir-6) ----
            float2 nm = make_float2(0.f, 0.f);
            int ni = 0;
            {
                const int mr = ir - 7;
                if ((unsigned)mr < (unsigned)W) {
                    // row ir-8 -> slot (j+2)&3 ; row ir-7 -> (j+3)&3 ; row ir-6 -> j&3
                    const float2& Am = ((j + 2) & 3) == 0 ? Ar0 : ((j + 2) & 3) == 1 ? Ar1
                                     : ((j + 2) & 3) == 2 ? Ar2 : Ar3;   // row mr-1
                    const float2& Ap = (j & 3) == 0 ? Ar0 : (j & 3) == 1 ? Ar1
                                     : (j & 3) == 2 ? Ar2 : Ar3;         // row mr+1
                    const float2& Bm = ((j + 2) & 3) == 0 ? Br0 : ((j + 2) & 3) == 1 ? Br1
                                     : ((j + 2) & 3) == 2 ? Br2 : Br3;   // row mr-1
                    const float2& Bc = ((j + 3) & 3) == 0 ? Br0 : ((j + 3) & 3) == 1 ? Br1
                                     : ((j + 3) & 3) == 2 ? Br2 : Br3;   // row mr
                    const float2& Bp = (j & 3) == 0 ? Br0 : (j & 3) == 1 ? Br1
                                     : (j & 3) == 2 ? Br2 : Br3;         // row mr+1
                    float gx0 = Bm.x + 2.0f * Bc.x + Bp.x;
                    float gy0 = Am.x - Ap.x;
                    nm.x = gx0 * gx0 + gy0 * gy0;
                    float gx1 = Bm.y + 2.0f * Bc.y + Bp.y;
                    float gy1 = Am.y - Ap.y;
                    nm.y = gx1 * gx1 + gy1 * gy1;
                    if (__any_sync(0xffffffffu, fmaxf(nm.x, nm.y) >= 4.0f))
                        ni = dir_idx(gx0, gy0) | (dir_idx(gx1, gy1) << 4) | 0x10000;
                }
            }

            __syncthreads();   // single barrier; post-barrier is stores + rare NMS

            // ---- STS prep row ir (transform inside guard: OOB rows store exact 0) ----
            {
                float2 p = make_float2(0.f, 0.f);
                if ((unsigned)ir < (unsigned)W)
                    p = make_float2((qa0 + 1.0f) * 0.5f, (qa1 + 1.0f) * 0.5f);
                sh_prep[(j + 2) & 3][t + 2] = p;
            }

            // ---- STS bl row ir-4 (slot (ir-4)&3 = (j+2)&3) ----
            sh_bl[(j + 2) & 3][t + 1] = v;

            // ---- STS mag row ir-7 (slot (ir-7)&3 = (j+3)&3) ----
            sh_mag[(j + 3) & 3][t + 1] = nm;

            // ---- NMS row er = ir-9 (center slot (ir-9)&3 = (j+1)&3); flag uniform ----
            {
                const int er = ir - 9;
                if ((unsigned)(er - r0) < (unsigned)BH && (d2i & 0x10000)) {
                    float2 cm = sh_mag[(j + 1) & 3][t + 1];   // own center mag^2
                    float e0 = nms_one(cm.x, d2i & 7,        mbase0, (j + 1) & 3);
                    float e1 = nms_one(cm.y, (d2i >> 4) & 7, mbase1, (j + 1) & 3);
                    acc += fabsf(e0 - e1);
                }
            }

            d2i = d1i; d1i = ni;
            qa0 = qb0; qa1 = qb1;
        }
    }

    // deterministic block reduction
    red[t] = acc;
    __syncthreads();
    #pragma unroll
    for (int off = 128; off > 0; off >>= 1) {
        if (t < off) red[t] += red[t + off];
        __syncthreads();
    }

    if (t == 0) {
        g_partials[blk] = red[0];
        __threadfence();
        unsigned old = atomicInc(&g_ticket, NBLOCKS - 1);   // wraps to 0 -> replay-safe
        s_last = (old == NBLOCKS - 1) ? 1u : 0u;
    }
    __syncthreads();

    // last block deterministically reduces all partials (double precision)
    if (s_last) {
        double s = 0.0;
        for (int i = t; i < NBLOCKS; i += 256) s += (double)__ldcg(&g_partials[i]);
        sdd[t] = s;
        __syncthreads();
        #pragma unroll
        for (int off = 128; off > 0; off >>= 1) {
            if (t < off) sdd[t] += sdd[t + off];
            __syncthreads();
        }
        if (t == 0) out[0] = (float)(sdd[0] / 8388608.0);
    }
}

extern "C" void kernel_launch(void* const* d_in, const int* in_sizes, int n_in,
                              void* d_out, int out_size) {
    const float* gt = (const float*)d_in[0];   // data_input
    const float* pr = (const float*)d_in[1];   // model_output
    canny_fused<<<NBLOCKS, 256>>>(gt, pr, (float*)d_out);
}

// round 16
// speedup vs baseline: 1.1082x; 1.0433x over previous
#include <cuda_runtime.h>
#include <cuda_bf16.h>
#include <cstdint>

#define W 256
#define BH 64
#define NBLOCKS 512           // 128 images * 4 bands
#define BMF 1032              // floats per sh_bm slot ((W+2) float4)

__device__ float g_partials[NBLOCKS];
__device__ unsigned int g_ticket;   // zero-init; atomicInc wraps after NBLOCKS -> graph-replay safe

// Gaussian taps as numpy computes them (f64 exp, f64 normalize)
constexpr double E2d  = 0.1353352832366127;   // exp(-2)
constexpr double E05d = 0.6065306597126334;   // exp(-0.5)
constexpr double GSUM = 1.0 + 2.0 * (E2d + E05d);
constexpr float  G0 = (float)(E2d / GSUM);
constexpr float  G1 = (float)(E05d / GSUM);
constexpr float  G2 = (float)(1.0 / GSUM);

// Quadrant-exact tangent thresholds for k = 4 + round(atan2(gy,gx)*4/3.14159)
#define TLO_POS 0.414213174f
#define THI_POS 2.414206767f
#define TLO_NEG 0.414216283f
#define THI_NEG 2.414224887f

__device__ __forceinline__ int dir_idx(float gx, float gy) {
    float ax = fabsf(gx), ay = fabsf(gy);
    bool xn = gx < 0.0f;
    float tlo = xn ? TLO_NEG : TLO_POS;
    float thi = xn ? THI_NEG : THI_POS;
    int s = (ay >= ax * tlo) ? ((ay > ax * thi) ? 2 : 1) : 0;
    int kp = xn ? (4 - s) : s;
    int k = (gy < 0.0f) ? (4 - kp) : (4 + kp);
    return k & 7;
}

// NMS neighbor offsets packed in nibbles: (dr+1),(dc+1) per idx (validated rel_err=0)
#define DRP 0x00012221u
#define DCP 0x21000122u

// Squared magnitudes; cslot = slot of center row (compile-time). Row er+dr lives in
// slot (cslot+dr)&3 because sh_bm slots advance 1 per row. Columns step 4 floats.
__device__ __forceinline__ float nms_one(float msq, int idx, const float* base, int cslot) {
    int dr = (int)((DRP >> (idx * 4)) & 3u) - 1;
    int dc = (int)((DCP >> (idx * 4)) & 3u) - 1;
    float np = base[((cslot + dr) & 3) * BMF + 4 * dc];
    float nn = base[((cslot - dr) & 3) * BMF - 4 * dc];
    bool pass = (fminf(msq - np, msq - nn) > 0.0f) && (msq >= 4.0f);
    return pass ? sqrtf(msq) : 0.0f;
}

// EDGE is a literal 0/1: guards compile away entirely for interior bands.
// Schedule (R12, proven): ir ≡ j (mod 4)
//  PRE : prefetch ir+1 | hblur ir-2 (prep slot (j+2)&3, written 2 iters ago) | vblur ir-4
//  POST: STS prep ir (slot j) | A/B ir-5 (bm slot (j+3)&3 bl half, written last iter;
//        center v_prev) -> named slot (j+3)&3 | magsq ir-6 (named slots j+1,j+2,j+3) |
//        STS bm slot j = {bl ir-4, mag ir-6} | NMS er=ir-8 (center slot (j+2)&3)
#define MAIN_LOOP(EDGE)                                                                     \
    for (int ir0 = r0 - 4; ir0 < r0 + BH + 8; ir0 += 4) {                                   \
        _Pragma("unroll")                                                                   \
        for (int j = 0; j < 4; ++j) {                                                       \
            const int ir = ir0 + j;                                                         \
            float qb0 = 0.f, qb1 = 0.f;                                                     \
            {                                                                               \
                const int irn = ir + 1;                                                     \
                if (!EDGE || (unsigned)irn < (unsigned)W) {                                 \
                    qb0 = b0[irn * W]; qb1 = b1[irn * W];                                   \
                }                                                                           \
            }                                                                               \
            float2 h;                                                                       \
            {                                                                               \
                const float2* pr = sh_prep[(j + 2) & 3];                                    \
                float2 a0 = pr[t], a1 = pr[t+1], a2 = pr[t+2], a3 = pr[t+3], a4 = pr[t+4];  \
                h.x = G0 * (a0.x + a4.x) + G1 * (a1.x + a3.x) + G2 * a2.x;                  \
                h.y = G0 * (a0.y + a4.y) + G1 * (a1.y + a3.y) + G2 * a2.y;                  \
            }                                                                               \
            hb0 = hb1; hb1 = hb2; hb2 = hb3; hb3 = hb4; hb4 = h;                            \
            float2 v = make_float2(0.f, 0.f);                                               \
            if (!EDGE || (unsigned)(ir - 4) < (unsigned)W) {                                \
                v.x = G0 * (hb0.x + hb4.x) + G1 * (hb1.x + hb3.x) + G2 * hb2.x;             \
                v.y = G0 * (hb0.y + hb4.y) + G1 * (hb1.y + hb3.y) + G2 * hb2.y;             \
            }                                                                               \
            __syncthreads();                                                                \
            {                                                                               \
                float2 p = make_float2(0.f, 0.f);                                           \
                if (!EDGE || (unsigned)ir < (unsigned)W)                                    \
                    p = make_float2((qa0 + 1.0f) * 0.5f, (qa1 + 1.0f) * 0.5f);              \
                sh_prep[j][t + 2] = p;                                                      \
            }                                                                               \
            {                                                                               \
                const float4* bm = sh_bm[(j + 3) & 3];                                      \
                float4 lq = bm[t], rq = bm[t + 2];                                          \
                float2 c = v_prev;                                                          \
                float2& Aw = ((j+3)&3)==0 ? Ar0 : ((j+3)&3)==1 ? Ar1                        \
                           : ((j+3)&3)==2 ? Ar2 : Ar3;                                      \
                float2& Bw = ((j+3)&3)==0 ? Br0 : ((j+3)&3)==1 ? Br1                        \
                           : ((j+3)&3)==2 ? Br2 : Br3;                                      \
                Aw.x = lq.x + 2.0f * c.x + rq.x;   Bw.x = lq.x - rq.x;                      \
                Aw.y = lq.y + 2.0f * c.y + rq.y;   Bw.y = lq.y - rq.y;                      \
            }                                                                               \
            v_prev = v;                                                                     \
            float2 nm = make_float2(0.f, 0.f);                                              \
            int ni = 0;                                                                     \
            if (!EDGE || (unsigned)(ir - 6) < (unsigned)W) {                                \
                const float2& Am = ((j+1)&3)==0 ? Ar0 : ((j+1)&3)==1 ? Ar1                  \
                                 : ((j+1)&3)==2 ? Ar2 : Ar3;                                \
                const float2& Ap = ((j+3)&3)==0 ? Ar0 : ((j+3)&3)==1 ? Ar1                  \
                                 : ((j+3)&3)==2 ? Ar2 : Ar3;                                \
                const float2& Bm = ((j+1)&3)==0 ? Br0 : ((j+1)&3)==1 ? Br1                  \
                                 : ((j+1)&3)==2 ? Br2 : Br3;                                \
                const float2& Bc = ((j+2)&3)==0 ? Br0 : ((j+2)&3)==1 ? Br1                  \
                                 : ((j+2)&3)==2 ? Br2 : Br3;                                \
                const float2& Bp = ((j+3)&3)==0 ? Br0 : ((j+3)&3)==1 ? Br1                  \
                                 : ((j+3)&3)==2 ? Br2 : Br3;                                \
                float gx0 = Bm.x + 2.0f * Bc.x + Bp.x;                                      \
                float gy0 = Am.x - Ap.x;                                                    \
                nm.x = gx0 * gx0 + gy0 * gy0;                                               \
                float gx1 = Bm.y + 2.0f * Bc.y + Bp.y;                                      \
                float gy1 = Am.y - Ap.y;                                                    \
                nm.y = gx1 * gx1 + gy1 * gy1;                                               \
                if (__any_sync(0xffffffffu, fmaxf(nm.x, nm.y) >= 4.0f))                     \
                    ni = dir_idx(gx0, gy0) | (dir_idx(gx1, gy1) << 4) | 0x10000;            \
            }                                                                               \
            sh_bm[j][t + 1] = make_float4(v.x, v.y, nm.x, nm.y);                            \
            {                                                                               \
                const int er = ir - 8;                                                      \
                if ((unsigned)(er - r0) < (unsigned)BH && (d2i & 0x10000)) {                \
                    const float* cbase = (const float*)&sh_bm[(j + 2) & 3][t + 1];          \
                    float e0 = nms_one(cbase[2], d2i & 7,        mbase0, (j + 2) & 3);      \
                    float e1 = nms_one(cbase[3], (d2i >> 4) & 7, mbase1, (j + 2) & 3);      \
                    acc += fabsf(e0 - e1);                                                  \
                }                                                                           \
            }                                                                               \
            d2i = d1i; d1i = ni;                                                            \
            qa0 = qb0; qa1 = qb1;                                                           \
        }                                                                                   \
    }

// float2/.x = image0, .y = image1; sh_bm float4 = {bl0, bl1, magsq0, magsq1}
__global__ __launch_bounds__(256, 4) void canny_fused(const float* __restrict__ in0,
                                                      const float* __restrict__ in1,
                                                      float* __restrict__ out) {
    const int t   = threadIdx.x;            // column
    const int blk = blockIdx.x;
    const int n   = blk >> 2;               // image
    const int r0  = (blk & 3) * BH;         // band start row (multiple of 64)
    const float* b0 = in0 + n * (W * W) + t;
    const float* b1 = in1 + n * (W * W) + t;

    __shared__ __align__(8)  float2 sh_prep[4][W + 4];  // col c -> idx c+2; guards 0,1,W+2,W+3
    __shared__ __align__(16) float4 sh_bm[4][W + 2];    // iteration-slot ring; col c -> idx c+1
    __shared__ float  red[256];
    __shared__ double sdd[256];
    __shared__ unsigned s_last;

    // zero everything once (guards stay zero; data cells get overwritten)
    {
        float2 z2 = make_float2(0.f, 0.f);
        float2* zp = (float2*)sh_prep;
        for (int i = t; i < 4 * (W + 4); i += 256) zp[i] = z2;
        float4 z4 = make_float4(0.f, 0.f, 0.f, 0.f);
        float4* zb = (float4*)sh_bm;
        for (int i = t; i < 4 * (W + 2); i += 256) zb[i] = z4;
    }

    // register state
    float2 hb0, hb1, hb2, hb3, hb4;                  // hblur rows ir-6..ir-2 (post-push)
    hb0 = hb1 = hb2 = hb3 = hb4 = make_float2(0.f, 0.f);
    float2 Ar0, Ar1, Ar2, Ar3, Br0, Br1, Br2, Br3;   // named A/B slots ((row)&3)
    Ar0 = Ar1 = Ar2 = Ar3 = Br0 = Br1 = Br2 = Br3 = make_float2(0.f, 0.f);
    float2 v_prev = make_float2(0.f, 0.f);           // vblur of row ir-5 (A/B center tap)
    int d1i = 0, d2i = 0;                            // dirs (bits 0-7) + pass flag (bit 16)
    float acc = 0.f;

    const float* mbase0 = (const float*)&sh_bm[0][t + 1] + 2;   // magsq image0
    const float* mbase1 = (const float*)&sh_bm[0][t + 1] + 3;   // magsq image1

    // software prefetch of the current row, one iteration ahead
    float qa0 = 0.f, qa1 = 0.f;
    {
        const int irf = r0 - 4;
        if ((unsigned)irf < (unsigned)W) { qa0 = b0[irf * W]; qa1 = b1[irf * W]; }
    }

    __syncthreads();

    // Interior bands never touch rows outside [0, W): rows span r0-4 .. r0+BH+8.
    const bool interior = (r0 >= 4) && (r0 + BH + 8 < W);
    if (interior) { MAIN_LOOP(0) } else { MAIN_LOOP(1) }

    // deterministic block reduction
    red[t] = acc;
    __syncthreads();
    #pragma unroll
    for (int off = 128; off > 0; off >>= 1) {
        if (t < off) red[t] += red[t + off];
        __syncthreads();
    }

    if (t == 0) {
        g_partials[blk] = red[0];
        __threadfence();
        unsigned old = atomicInc(&g_ticket, NBLOCKS - 1);   // wraps to 0 -> replay-safe
        s_last = (old == NBLOCKS - 1) ? 1u : 0u;
    }
    __syncthreads();

    // last block deterministically reduces all partials (double precision)
    if (s_last) {
        double s = 0.0;
        for (int i = t; i < NBLOCKS; i += 256) s += (double)__ldcg(&g_partials[i]);
        sdd[t] = s;
        __syncthreads();
        #pragma unroll
        for (int off = 128; off > 0; off >>= 1) {
            if (t < off) sdd[t] += sdd[t + off];
            __syncthreads();
        }
        if (t == 0) out[0] = (float)(sdd[0] / 8388608.0);
    }
}

extern "C" void kernel_launch(void* const* d_in, const int* in_sizes, int n_in,
                              void* d_out, int out_size) {
    const float* gt = (const float*)d_in[0];   // data_input
    const float* pr = (const float*)d_in[1];   // model_output
    canny_fused<<<NBLOCKS, 256>>>(gt, pr, (float*)d_out);
}

// round 17
// speedup vs baseline: 1.1215x; 1.0120x over previous
#include <cuda_runtime.h>
#include <cuda_bf16.h>
#include <cstdint>

#define W 256
#define BH 64
#define NBLOCKS 512           // 128 images * 4 bands
#define MAGF 516              // floats per sh_mag slot ((W+2) float2)

__device__ float g_partials[NBLOCKS];
__device__ unsigned int g_ticket;   // zero-init; atomicInc wraps after NBLOCKS -> graph-replay safe

// Gaussian taps as numpy computes them (f64 exp, f64 normalize)
constexpr double E2d  = 0.1353352832366127;   // exp(-2)
constexpr double E05d = 0.6065306597126334;   // exp(-0.5)
constexpr double GSUM = 1.0 + 2.0 * (E2d + E05d);
constexpr float  G0 = (float)(E2d / GSUM);
constexpr float  G1 = (float)(E05d / GSUM);
constexpr float  G2 = (float)(1.0 / GSUM);

// Quadrant-exact tangent thresholds for k = 4 + round(atan2(gy,gx)*4/3.14159)
#define TLO_POS 0.414213174f
#define THI_POS 2.414206767f
#define TLO_NEG 0.414216283f
#define THI_NEG 2.414224887f

__device__ __forceinline__ int dir_idx(float gx, float gy) {
    float ax = fabsf(gx), ay = fabsf(gy);
    bool xn = gx < 0.0f;
    float tlo = xn ? TLO_NEG : TLO_POS;
    float thi = xn ? THI_NEG : THI_POS;
    int s = (ay >= ax * tlo) ? ((ay > ax * thi) ? 2 : 1) : 0;
    int kp = xn ? (4 - s) : s;
    int k = (gy < 0.0f) ? (4 - kp) : (4 + kp);
    return k & 7;
}

// NMS neighbor offsets packed in nibbles: (dr+1),(dc+1) per idx (validated rel_err=0)
#define DRP 0x00012221u
#define DCP 0x21000122u

// Squared magnitudes; cslot = slot holding center row er (compile-time). Row er+dr
// lives in slot (cslot+dr)&3 (slots advance 1 per row). Columns step 2 floats.
__device__ __forceinline__ float nms_one(float msq, int idx, const float* base, int cslot) {
    int dr = (int)((DRP >> (idx * 4)) & 3u) - 1;
    int dc = (int)((DCP >> (idx * 4)) & 3u) - 1;
    float np = base[((cslot + dr) & 3) * MAGF + 2 * dc];
    float nn = base[((cslot - dr) & 3) * MAGF - 2 * dc];
    bool pass = (fminf(msq - np, msq - nn) > 0.0f) && (msq >= 4.0f);
    return pass ? sqrtf(msq) : 0.0f;
}

// EDGE is a literal 0/1: guards compile away entirely for interior bands.
// Schedule (R12/R16, proven): ir ≡ j (mod 4)
//  PRE : prefetch ir+1 | hblur ir-2 (prep slot (j+2)&3, written 2 iters ago) | vblur ir-4
//  POST: STS prep ir (slot j) | A/B ir-5 (bl slot (j+3)&3, written last iter;
//        center v_prev) -> named reg slot (j+3)&3 | magsq ir-6 (named slots j+1,j+2,j+3) |
//        STS bl ir-4 (slot j) | STS mag ir-6 (slot j) | NMS er=ir-8 (center slot (j+2)&3;
//        neighbor slots (j+1)&3,(j+3)&3 — disjoint from write slot j, barrier-separated)
#define MAIN_LOOP(EDGE)                                                                     \
    for (int ir0 = r0 - 4; ir0 < r0 + BH + 8; ir0 += 4) {                                   \
        _Pragma("unroll")                                                                   \
        for (int j = 0; j < 4; ++j) {                                                       \
            const int ir = ir0 + j;                                                         \
            float qb0 = 0.f, qb1 = 0.f;                                                     \
            {                                                                               \
                const int irn = ir + 1;                                                     \
                if (!EDGE || (unsigned)irn < (unsigned)W) {                                 \
                    qb0 = b0[irn * W]; qb1 = b1[irn * W];                                   \
                }                                                                           \
            }                                                                               \
            float2 h;                                                                       \
            {                                                                               \
                const float2* pr = sh_prep[(j + 2) & 3];                                    \
                float2 a0 = pr[t], a1 = pr[t+1], a2 = pr[t+2], a3 = pr[t+3], a4 = pr[t+4];  \
                h.x = G0 * (a0.x + a4.x) + G1 * (a1.x + a3.x) + G2 * a2.x;                  \
                h.y = G0 * (a0.y + a4.y) + G1 * (a1.y + a3.y) + G2 * a2.y;                  \
            }                                                                               \
            hb0 = hb1; hb1 = hb2; hb2 = hb3; hb3 = hb4; hb4 = h;                            \
            float2 v = make_float2(0.f, 0.f);                                               \
            if (!EDGE || (unsigned)(ir - 4) < (unsigned)W) {                                \
                v.x = G0 * (hb0.x + hb4.x) + G1 * (hb1.x + hb3.x) + G2 * hb2.x;             \
                v.y = G0 * (hb0.y + hb4.y) + G1 * (hb1.y + hb3.y) + G2 * hb2.y;             \
            }                                                                               \
            __syncthreads();                                                                \
            {                                                                               \
                float2 p = make_float2(0.f, 0.f);                                           \
                if (!EDGE || (unsigned)ir < (unsigned)W)                                    \
                    p = make_float2((qa0 + 1.0f) * 0.5f, (qa1 + 1.0f) * 0.5f);              \
                sh_prep[j][t + 2] = p;                                                      \
            }                                                                               \
            {                                                                               \
                const float2* bl = sh_bl[(j + 3) & 3];                                      \
                float2 l = bl[t], r = bl[t + 2];                                            \
                float2 c = v_prev;                                                          \
                float2& Aw = ((j+3)&3)==0 ? Ar0 : ((j+3)&3)==1 ? Ar1                        \
                           : ((j+3)&3)==2 ? Ar2 : Ar3;                                      \
                float2& Bw = ((j+3)&3)==0 ? Br0 : ((j+3)&3)==1 ? Br1                        \
                           : ((j+3)&3)==2 ? Br2 : Br3;                                      \
                Aw.x = l.x + 2.0f * c.x + r.x;   Bw.x = l.x - r.x;                          \
                Aw.y = l.y + 2.0f * c.y + r.y;   Bw.y = l.y - r.y;                          \
            }                                                                               \
            v_prev = v;                                                                     \
            float2 nm = make_float2(0.f, 0.f);                                              \
            int ni = 0;                                                                     \
            if (!EDGE || (unsigned)(ir - 6) < (unsigned)W) {                                \
                const float2& Am = ((j+1)&3)==0 ? Ar0 : ((j+1)&3)==1 ? Ar1                  \
                                 : ((j+1)&3)==2 ? Ar2 : Ar3;                                \
                const float2& Ap = ((j+3)&3)==0 ? Ar0 : ((j+3)&3)==1 ? Ar1                  \
                                 : ((j+3)&3)==2 ? Ar2 : Ar3;                                \
                const float2& Bm = ((j+1)&3)==0 ? Br0 : ((j+1)&3)==1 ? Br1                  \
                                 : ((j+1)&3)==2 ? Br2 : Br3;                                \
                const float2& Bc = ((j+2)&3)==0 ? Br0 : ((j+2)&3)==1 ? Br1                  \
                                 : ((j+2)&3)==2 ? Br2 : Br3;                                \
                const float2& Bp = ((j+3)&3)==0 ? Br0 : ((j+3)&3)==1 ? Br1                  \
                                 : ((j+3)&3)==2 ? Br2 : Br3;                                \
                float gx0 = Bm.x + 2.0f * Bc.x + Bp.x;                                      \
                float gy0 = Am.x - Ap.x;                                                    \
                nm.x = gx0 * gx0 + gy0 * gy0;                                               \
                float gx1 = Bm.y + 2.0f * Bc.y + Bp.y;                                      \
                float gy1 = Am.y - Ap.y;                                                    \
                nm.y = gx1 * gx1 + gy1 * gy1;                                               \
                if (__any_sync(0xffffffffu, fmaxf(nm.x, nm.y) >= 4.0f))                     \
                    ni = dir_idx(gx0, gy0) | (dir_idx(gx1, gy1) << 4) | 0x10000;            \
            }                                                                               \
            sh_bl[j][t + 1]  = v;                                                           \
            sh_mag[j][t + 1] = nm;                                                          \
            {                                                                               \
                const int er = ir - 8;                                                      \
                if ((unsigned)(er - r0) < (unsigned)BH && (d2i & 0x10000)) {                \
                    float2 cm = sh_mag[(j + 2) & 3][t + 1];                                 \
                    float e0 = nms_one(cm.x, d2i & 7,        mbase0, (j + 2) & 3);          \
                    float e1 = nms_one(cm.y, (d2i >> 4) & 7, mbase1, (j + 2) & 3);          \
                    acc += fabsf(e0 - e1);                                                  \
                }                                                                           \
            }                                                                               \
            d2i = d1i; d1i = ni;                                                            \
            qa0 = qb0; qa1 = qb1;                                                           \
        }                                                                                   \
    }

// float2 layout everywhere: .x = image0, .y = image1
__global__ __launch_bounds__(256, 4) void canny_fused(const float* __restrict__ in0,
                                                      const float* __restrict__ in1,
                                                      float* __restrict__ out) {
    const int t   = threadIdx.x;            // column
    const int blk = blockIdx.x;
    const int n   = blk >> 2;               // image
    const int r0  = (blk & 3) * BH;         // band start row (multiple of 64)
    const float* b0 = in0 + n * (W * W) + t;
    const float* b1 = in1 + n * (W * W) + t;

    __shared__ __align__(8) float2 sh_prep[4][W + 4];   // col c -> idx c+2; guards 0,1,W+2,W+3
    __shared__ __align__(8) float2 sh_bl[4][W + 2];     // iteration-slot ring; col c -> idx c+1
    __shared__ __align__(8) float2 sh_mag[4][W + 2];    // SQUARED mags; col c -> idx c+1
    __shared__ float  red[256];
    __shared__ double sdd[256];
    __shared__ unsigned s_last;

    // zero everything once (guards stay zero; data cells get overwritten)
    {
        float2 z = make_float2(0.f, 0.f);
        float2* zp = (float2*)sh_prep;
        for (int i = t; i < 4 * (W + 4); i += 256) zp[i] = z;
        float2* zb = (float2*)sh_bl;
        for (int i = t; i < 4 * (W + 2); i += 256) zb[i] = z;
        float2* zm = (float2*)sh_mag;
        for (int i = t; i < 4 * (W + 2); i += 256) zm[i] = z;
    }

    // register state
    float2 hb0, hb1, hb2, hb3, hb4;                  // hblur rows ir-6..ir-2 (post-push)
    hb0 = hb1 = hb2 = hb3 = hb4 = make_float2(0.f, 0.f);
    float2 Ar0, Ar1, Ar2, Ar3, Br0, Br1, Br2, Br3;   // named A/B slots ((row)&3)
    Ar0 = Ar1 = Ar2 = Ar3 = Br0 = Br1 = Br2 = Br3 = make_float2(0.f, 0.f);
    float2 v_prev = make_float2(0.f, 0.f);           // vblur of row ir-5 (A/B center tap)
    int d1i = 0, d2i = 0;                            // dirs (bits 0-7) + pass flag (bit 16)
    float acc = 0.f;

    const float* mbase0 = &sh_mag[0][t + 1].x;
    const float* mbase1 = &sh_mag[0][t + 1].y;

    // software prefetch of the current row, one iteration ahead
    float qa0 = 0.f, qa1 = 0.f;
    {
        const int irf = r0 - 4;
        if ((unsigned)irf < (unsigned)W) { qa0 = b0[irf * W]; qa1 = b1[irf * W]; }
    }

    __syncthreads();

    // Interior bands never touch rows outside [0, W): rows span r0-4 .. r0+BH+8.
    const bool interior = (r0 >= 4) && (r0 + BH + 8 < W);
    if (interior) { MAIN_LOOP(0) } else { MAIN_LOOP(1) }

    // deterministic block reduction
    red[t] = acc;
    __syncthreads();
    #pragma unroll
    for (int off = 128; off > 0; off >>= 1) {
        if (t < off) red[t] += red[t + off];
        __syncthreads();
    }

    if (t == 0) {
        g_partials[blk] = red[0];
        __threadfence();
        unsigned old = atomicInc(&g_ticket, NBLOCKS - 1);   // wraps to 0 -> replay-safe
        s_last = (old == NBLOCKS - 1) ? 1u : 0u;
    }
    __syncthreads();

    // last block deterministically reduces all partials (double precision)
    if (s_last) {
        double s = 0.0;
        for (int i = t; i < NBLOCKS; i += 256) s += (double)__ldcg(&g_partials[i]);
        sdd[t] = s;
        __syncthreads();
        #pragma unroll
        for (int off = 128; off > 0; off >>= 1) {
            if (t < off) sdd[t] += sdd[t + off];
            __syncthreads();
        }
        if (t == 0) out[0] = (float)(sdd[0] / 8388608.0);
    }
}

extern "C" void kernel_launch(void* const* d_in, const int* in_sizes, int n_in,
                              void* d_out, int out_size) {
    const float* gt = (const float*)d_in[0];   // data_input
    const float* pr = (const float*)d_in[1];   // model_output
    canny_fused<<<NBLOCKS, 256>>>(gt, pr, (float*)d_out);
}